// round 4
// baseline (speedup 1.0000x reference)
#include <cuda_runtime.h>

#define NNODES 50000
#define DD 16
#define BB 32
#define NDRVN 500
#define FEAT 5
#define NMID 5

// Ping-pong state buffers, node-major [N, B]
__device__ float g_zA[NNODES * BB];
__device__ float g_zB[NNODES * BB];

// ---------------------------------------------------------------------------
// Transpose x [B, N] -> g_zA [N, B]
// ---------------------------------------------------------------------------
__global__ void transpose_kernel(const float* __restrict__ x) {
    __shared__ float tile[32][33];
    int n0 = blockIdx.x * 32;
    int tx = threadIdx.x, ty = threadIdx.y;
    int n = n0 + tx;
    if (n < NNODES) tile[ty][tx] = x[ty * NNODES + n];
    __syncthreads();
    int n2 = n0 + ty;
    if (n2 < NNODES) g_zA[n2 * BB + tx] = tile[tx][ty];
}

// ---------------------------------------------------------------------------
// Mid conv layer, co-outer / position-inner: 15 weights live in registers,
// reused across all output positions. hin/hout ping-pong (no copies).
// ---------------------------------------------------------------------------
template <int WIN, int AW, int BW>
__device__ __forceinline__ void mid_layer(const float (&hin)[FEAT][AW],
                                          float (&hout)[FEAT][BW],
                                          const float* __restrict__ sw,
                                          const float* __restrict__ sb) {
    #pragma unroll
    for (int co = 0; co < FEAT; co++) {
        // weights for this output channel -> registers (loop-invariant over w)
        float wr[FEAT * 3];
        #pragma unroll
        for (int i = 0; i < FEAT * 3; i++) wr[i] = sw[(co * FEAT) * 3 + i];
        float bias = sb[co];
        #pragma unroll
        for (int w = 0; w < WIN - 2; w++) {
            float a = bias;
            #pragma unroll
            for (int ci = 0; ci < FEAT; ci++) {
                a = fmaf(wr[ci * 3 + 0], hin[ci][w + 0], a);
                a = fmaf(wr[ci * 3 + 1], hin[ci][w + 1], a);
                a = fmaf(wr[ci * 3 + 2], hin[ci][w + 2], a);
            }
            hout[co][w] = fmaxf(a, 0.0f);
        }
    }
}

// ---------------------------------------------------------------------------
// One message pass: gather, 7 convs + relu, avgpool.  warp=node, lane=batch
// ---------------------------------------------------------------------------
template <int SRC>   // SRC=0: read g_zA write g_zB;  SRC=1: read g_zB write g_zA
__global__ void __launch_bounds__(128)
pass_kernel(const int* __restrict__ nbr,
            const float* __restrict__ w_first, const float* __restrict__ b_first,
            const float* __restrict__ w_mid,   const float* __restrict__ b_mid,
            const float* __restrict__ w_last,  const float* __restrict__ b_last) {
    __shared__ float swf[FEAT * 3];
    __shared__ float sbf[FEAT];
    __shared__ float swm[NMID * FEAT * FEAT * 3];
    __shared__ float sbm[NMID * FEAT];
    __shared__ float swl[FEAT * 3];
    __shared__ float sbl[1];

    int t = threadIdx.x;
    if (t < FEAT * 3) swf[t] = w_first[t];
    if (t < FEAT) sbf[t] = b_first[t];
    for (int i = t; i < NMID * FEAT * FEAT * 3; i += blockDim.x) swm[i] = w_mid[i];
    if (t < NMID * FEAT) sbm[t] = b_mid[t];
    if (t < FEAT * 3) swl[t] = w_last[t];
    if (t == 0) sbl[0] = b_last[0];
    __syncthreads();

    const float* __restrict__ zin = SRC == 0 ? g_zA : g_zB;
    float* __restrict__ zout      = SRC == 0 ? g_zB : g_zA;

    unsigned gid = blockIdx.x * blockDim.x + threadIdx.x;
    if (gid >= (unsigned)NNODES * BB) return;
    int n = gid >> 5;   // node (warp-uniform)
    int b = gid & 31;   // batch = lane

    // Gather 16 neighbor states (idx warp-uniform, data coalesced)
    float v[DD];
    const int* nb = nbr + n * DD;
    #pragma unroll
    for (int d = 0; d < DD; d++) {
        int idx = __ldg(&nb[d]);
        v[d] = __ldg(&zin[idx * BB + b]);
    }

    // First conv: 1 -> 5 channels, width 16 -> 14 (weights hoisted to regs)
    float hA[FEAT][14];
    {
        float wr[FEAT * 3];
        #pragma unroll
        for (int i = 0; i < FEAT * 3; i++) wr[i] = swf[i];
        #pragma unroll
        for (int c = 0; c < FEAT; c++) {
            float bias = sbf[c];
            #pragma unroll
            for (int w = 0; w < 14; w++) {
                float a = bias;
                a = fmaf(wr[c * 3 + 0], v[w + 0], a);
                a = fmaf(wr[c * 3 + 1], v[w + 1], a);
                a = fmaf(wr[c * 3 + 2], v[w + 2], a);
                hA[c][w] = fmaxf(a, 0.0f);
            }
        }
    }

    // 5 middle convs: 14->12->10->8->6->4, ping-pong hA <-> hB
    float hB[FEAT][12];
    mid_layer<14>(hA, hB, swm + 0 * FEAT * FEAT * 3, sbm + 0 * FEAT);
    mid_layer<12>(hB, hA, swm + 1 * FEAT * FEAT * 3, sbm + 1 * FEAT);
    mid_layer<10>(hA, hB, swm + 2 * FEAT * FEAT * 3, sbm + 2 * FEAT);
    mid_layer<8>(hB, hA,  swm + 3 * FEAT * FEAT * 3, sbm + 3 * FEAT);
    mid_layer<6>(hA, hB,  swm + 4 * FEAT * FEAT * 3, sbm + 4 * FEAT);

    // Last conv: 5 -> 1 channel, width 4 -> 2, relu, avgpool(2)
    float o[2];
    {
        float wr[FEAT * 3];
        #pragma unroll
        for (int i = 0; i < FEAT * 3; i++) wr[i] = swl[i];
        float bias = sbl[0];
        #pragma unroll
        for (int w = 0; w < 2; w++) {
            float a = bias;
            #pragma unroll
            for (int ci = 0; ci < FEAT; ci++) {
                a = fmaf(wr[ci * 3 + 0], hB[ci][w + 0], a);
                a = fmaf(wr[ci * 3 + 1], hB[ci][w + 1], a);
                a = fmaf(wr[ci * 3 + 2], hB[ci][w + 2], a);
            }
            o[w] = fmaxf(a, 0.0f);
        }
    }
    zout[n * BB + b] = 0.5f * (o[0] + o[1]);
}

// ---------------------------------------------------------------------------
// Zero fill the output (poisoned before timing)
// ---------------------------------------------------------------------------
__global__ void zero_kernel(float4* __restrict__ out, int n4) {
    int i = blockIdx.x * blockDim.x + threadIdx.x;
    if (i < n4) out[i] = make_float4(0.f, 0.f, 0.f, 0.f);
}

// ---------------------------------------------------------------------------
// Masked softmax over driver columns only; final state in g_zA
// ---------------------------------------------------------------------------
__global__ void softmax_kernel(const int* __restrict__ drivers,
                               float* __restrict__ out) {
    __shared__ float red[512];
    int b = blockIdx.x;
    int t = threadIdx.x;

    float myv = 0.0f;
    int drv = -1;
    float mval = -INFINITY;
    if (t < NDRVN) {
        drv = drivers[t];
        myv = g_zA[drv * BB + b];
        mval = myv;
    }
    red[t] = mval;
    __syncthreads();
    #pragma unroll
    for (int s = 256; s > 0; s >>= 1) {
        if (t < s) red[t] = fmaxf(red[t], red[t + s]);
        __syncthreads();
    }
    float m = fmaxf(red[0], 0.0f);
    __syncthreads();

    float e = (t < NDRVN) ? expf(myv - m) : 0.0f;
    red[t] = e;
    __syncthreads();
    #pragma unroll
    for (int s = 256; s > 0; s >>= 1) {
        if (t < s) red[t] += red[t + s];
        __syncthreads();
    }
    float Z = red[0] + (float)(NNODES - NDRVN) * expf(-m);

    if (t < NDRVN) out[b * NNODES + drv] = e / Z;
}

// ---------------------------------------------------------------------------
extern "C" void kernel_launch(void* const* d_in, const int* in_sizes, int n_in,
                              void* d_out, int out_size) {
    const float* x       = (const float*)d_in[0];
    const int*   nbr     = (const int*)  d_in[1];
    const int*   drivers = (const int*)  d_in[2];
    // d_in[3] = driver_matrix (unused)
    const float* w_first = (const float*)d_in[4];
    const float* b_first = (const float*)d_in[5];
    const float* w_mid   = (const float*)d_in[6];
    const float* b_mid   = (const float*)d_in[7];
    const float* w_last  = (const float*)d_in[8];
    const float* b_last  = (const float*)d_in[9];
    float* out = (float*)d_out;

    transpose_kernel<<<(NNODES + 31) / 32, dim3(32, 32)>>>(x);

    const int total = NNODES * BB;          // 1,600,000 threads
    const int blk = 128;
    const int grid = (total + blk - 1) / blk;

    pass_kernel<0><<<grid, blk>>>(nbr, w_first, b_first, w_mid, b_mid, w_last, b_last);
    pass_kernel<1><<<grid, blk>>>(nbr, w_first, b_first, w_mid, b_mid, w_last, b_last);
    pass_kernel<0><<<grid, blk>>>(nbr, w_first, b_first, w_mid, b_mid, w_last, b_last);
    pass_kernel<1><<<grid, blk>>>(nbr, w_first, b_first, w_mid, b_mid, w_last, b_last);

    int n4 = NNODES * BB / 4;
    zero_kernel<<<(n4 + 255) / 256, 256>>>((float4*)out, n4);
    softmax_kernel<<<BB, 512>>>(drivers, out);
}

// round 6
// speedup vs baseline: 1.0287x; 1.0287x over previous
#include <cuda_runtime.h>

#define NNODES 50000
#define DD 16
#define BB 32
#define NDRVN 500
#define FEAT 5
#define NMID 5

// Ping-pong state buffers, node-major [N, B]
__device__ float g_zA[NNODES * BB];
__device__ float g_zB[NNODES * BB];

// ---------------------------------------------------------------------------
// Transpose x [B, N] -> g_zA [N, B]
// ---------------------------------------------------------------------------
__global__ void transpose_kernel(const float* __restrict__ x) {
    __shared__ float tile[32][33];
    int n0 = blockIdx.x * 32;
    int tx = threadIdx.x, ty = threadIdx.y;
    int n = n0 + tx;
    if (n < NNODES) tile[ty][tx] = x[ty * NNODES + n];
    __syncthreads();
    int n2 = n0 + ty;
    if (n2 < NNODES) g_zA[n2 * BB + tx] = tile[tx][ty];
}

// ---------------------------------------------------------------------------
// Mid conv layer, co-outer / position-inner
// ---------------------------------------------------------------------------
template <int WIN, int AW, int BW>
__device__ __forceinline__ void mid_layer(const float (&hin)[FEAT][AW],
                                          float (&hout)[FEAT][BW],
                                          const float* __restrict__ sw,
                                          const float* __restrict__ sb) {
    #pragma unroll
    for (int co = 0; co < FEAT; co++) {
        float wr[FEAT * 3];
        #pragma unroll
        for (int i = 0; i < FEAT * 3; i++) wr[i] = sw[(co * FEAT) * 3 + i];
        float bias = sb[co];
        #pragma unroll
        for (int w = 0; w < WIN - 2; w++) {
            float a = bias;
            #pragma unroll
            for (int ci = 0; ci < FEAT; ci++) {
                a = fmaf(wr[ci * 3 + 0], hin[ci][w + 0], a);
                a = fmaf(wr[ci * 3 + 1], hin[ci][w + 1], a);
                a = fmaf(wr[ci * 3 + 2], hin[ci][w + 2], a);
            }
            hout[co][w] = fmaxf(a, 0.0f);
        }
    }
}

// ---------------------------------------------------------------------------
// Shared pass body (warp=node, lane=batch)
// ---------------------------------------------------------------------------
__device__ __forceinline__ void pass_body(
        const float* __restrict__ zin, float* __restrict__ zout,
        const int* __restrict__ nbr,
        const float* __restrict__ w_first, const float* __restrict__ b_first,
        const float* __restrict__ w_mid,   const float* __restrict__ b_mid,
        const float* __restrict__ w_last,  const float* __restrict__ b_last) {
    __shared__ float swf[FEAT * 3];
    __shared__ float sbf[FEAT];
    __shared__ float swm[NMID * FEAT * FEAT * 3];
    __shared__ float sbm[NMID * FEAT];
    __shared__ float swl[FEAT * 3];
    __shared__ float sbl[1];

    int t = threadIdx.x;
    if (t < FEAT * 3) swf[t] = w_first[t];
    if (t < FEAT) sbf[t] = b_first[t];
    for (int i = t; i < NMID * FEAT * FEAT * 3; i += blockDim.x) swm[i] = w_mid[i];
    if (t < NMID * FEAT) sbm[t] = b_mid[t];
    if (t < FEAT * 3) swl[t] = w_last[t];
    if (t == 0) sbl[0] = b_last[0];
    __syncthreads();

    unsigned gid = blockIdx.x * blockDim.x + threadIdx.x;
    if (gid >= (unsigned)NNODES * BB) return;
    int n = gid >> 5;
    int b = gid & 31;

    // Gather 16 neighbor states (idx warp-uniform, data coalesced)
    float v[DD];
    const int* nb = nbr + n * DD;
    #pragma unroll
    for (int d = 0; d < DD; d++) {
        int idx = __ldg(&nb[d]);
        v[d] = __ldg(&zin[idx * BB + b]);
    }

    // First conv: 1 -> 5 channels, width 16 -> 14
    float hA[FEAT][14];
    {
        float wr[FEAT * 3];
        #pragma unroll
        for (int i = 0; i < FEAT * 3; i++) wr[i] = swf[i];
        #pragma unroll
        for (int c = 0; c < FEAT; c++) {
            float bias = sbf[c];
            #pragma unroll
            for (int w = 0; w < 14; w++) {
                float a = bias;
                a = fmaf(wr[c * 3 + 0], v[w + 0], a);
                a = fmaf(wr[c * 3 + 1], v[w + 1], a);
                a = fmaf(wr[c * 3 + 2], v[w + 2], a);
                hA[c][w] = fmaxf(a, 0.0f);
            }
        }
    }

    // 5 middle convs: 14->12->10->8->6->4, ping-pong hA <-> hB
    float hB[FEAT][12];
    mid_layer<14>(hA, hB, swm + 0 * FEAT * FEAT * 3, sbm + 0 * FEAT);
    mid_layer<12>(hB, hA, swm + 1 * FEAT * FEAT * 3, sbm + 1 * FEAT);
    mid_layer<10>(hA, hB, swm + 2 * FEAT * FEAT * 3, sbm + 2 * FEAT);
    mid_layer<8>(hB, hA,  swm + 3 * FEAT * FEAT * 3, sbm + 3 * FEAT);
    mid_layer<6>(hA, hB,  swm + 4 * FEAT * FEAT * 3, sbm + 4 * FEAT);

    // Last conv: 5 -> 1 channel, width 4 -> 2, relu, avgpool(2)
    float o[2];
    {
        float wr[FEAT * 3];
        #pragma unroll
        for (int i = 0; i < FEAT * 3; i++) wr[i] = swl[i];
        float bias = sbl[0];
        #pragma unroll
        for (int w = 0; w < 2; w++) {
            float a = bias;
            #pragma unroll
            for (int ci = 0; ci < FEAT; ci++) {
                a = fmaf(wr[ci * 3 + 0], hB[ci][w + 0], a);
                a = fmaf(wr[ci * 3 + 1], hB[ci][w + 1], a);
                a = fmaf(wr[ci * 3 + 2], hB[ci][w + 2], a);
            }
            o[w] = fmaxf(a, 0.0f);
        }
    }
    zout[n * BB + b] = 0.5f * (o[0] + o[1]);
}

// Variant A: register cap 128 -> 4 blocks/SM (16 warps), may spill a little
template <int SRC>
__global__ void __launch_bounds__(128, 4)
pass_hiocc(const int* __restrict__ nbr,
           const float* __restrict__ w_first, const float* __restrict__ b_first,
           const float* __restrict__ w_mid,   const float* __restrict__ b_mid,
           const float* __restrict__ w_last,  const float* __restrict__ b_last) {
    pass_body(SRC == 0 ? g_zA : g_zB, SRC == 0 ? g_zB : g_zA,
              nbr, w_first, b_first, w_mid, b_mid, w_last, b_last);
}

// Variant B: R4 baseline (147 regs, 3 blocks/SM)
template <int SRC>
__global__ void __launch_bounds__(128)
pass_base(const int* __restrict__ nbr,
          const float* __restrict__ w_first, const float* __restrict__ b_first,
          const float* __restrict__ w_mid,   const float* __restrict__ b_mid,
          const float* __restrict__ w_last,  const float* __restrict__ b_last) {
    pass_body(SRC == 0 ? g_zA : g_zB, SRC == 0 ? g_zB : g_zA,
              nbr, w_first, b_first, w_mid, b_mid, w_last, b_last);
}

// ---------------------------------------------------------------------------
__global__ void zero_kernel(float4* __restrict__ out, int n4) {
    int i = blockIdx.x * blockDim.x + threadIdx.x;
    if (i < n4) out[i] = make_float4(0.f, 0.f, 0.f, 0.f);
}

// ---------------------------------------------------------------------------
// Masked softmax over driver columns only; final state in g_zA
// ---------------------------------------------------------------------------
__global__ void softmax_kernel(const int* __restrict__ drivers,
                               float* __restrict__ out) {
    __shared__ float red[512];
    int b = blockIdx.x;
    int t = threadIdx.x;

    float myv = 0.0f;
    int drv = -1;
    float mval = -INFINITY;
    if (t < NDRVN) {
        drv = drivers[t];
        myv = g_zA[drv * BB + b];
        mval = myv;
    }
    red[t] = mval;
    __syncthreads();
    #pragma unroll
    for (int s = 256; s > 0; s >>= 1) {
        if (t < s) red[t] = fmaxf(red[t], red[t + s]);
        __syncthreads();
    }
    float m = fmaxf(red[0], 0.0f);
    __syncthreads();

    float e = (t < NDRVN) ? expf(myv - m) : 0.0f;
    red[t] = e;
    __syncthreads();
    #pragma unroll
    for (int s = 256; s > 0; s >>= 1) {
        if (t < s) red[t] += red[t + s];
        __syncthreads();
    }
    float Z = red[0] + (float)(NNODES - NDRVN) * expf(-m);

    if (t < NDRVN) out[b * NNODES + drv] = e / Z;
}

// ---------------------------------------------------------------------------
extern "C" void kernel_launch(void* const* d_in, const int* in_sizes, int n_in,
                              void* d_out, int out_size) {
    const float* x       = (const float*)d_in[0];
    const int*   nbr     = (const int*)  d_in[1];
    const int*   drivers = (const int*)  d_in[2];
    // d_in[3] = driver_matrix (unused)
    const float* w_first = (const float*)d_in[4];
    const float* b_first = (const float*)d_in[5];
    const float* w_mid   = (const float*)d_in[6];
    const float* b_mid   = (const float*)d_in[7];
    const float* w_last  = (const float*)d_in[8];
    const float* b_last  = (const float*)d_in[9];
    float* out = (float*)d_out;

    transpose_kernel<<<(NNODES + 31) / 32, dim3(32, 32)>>>(x);

    const int total = NNODES * BB;
    const int blk = 128;
    const int grid = (total + blk - 1) / blk;

    // A/B experiment: passes 1-2 high-occupancy variant, passes 3-4 baseline
    pass_hiocc<0><<<grid, blk>>>(nbr, w_first, b_first, w_mid, b_mid, w_last, b_last);
    pass_hiocc<1><<<grid, blk>>>(nbr, w_first, b_first, w_mid, b_mid, w_last, b_last);
    pass_base<0><<<grid, blk>>>(nbr, w_first, b_first, w_mid, b_mid, w_last, b_last);
    pass_base<1><<<grid, blk>>>(nbr, w_first, b_first, w_mid, b_mid, w_last, b_last);

    int n4 = NNODES * BB / 4;
    zero_kernel<<<(n4 + 255) / 256, 256>>>((float4*)out, n4);
    softmax_kernel<<<BB, 512>>>(drivers, out);
}

// round 7
// speedup vs baseline: 1.8447x; 1.7933x over previous
#include <cuda_runtime.h>

#define NNODES 50000
#define DD 16
#define BB 32
#define NPAIR 16
#define NDRVN 500
#define FEAT 5
#define NMID 5

typedef unsigned long long u64;

// State buffers
__device__ float g_zA[NNODES * BB];              // z after transpose / pass2
__device__ float g_zB[NNODES * BB];              // z after pass1
__device__ float g_z3[NDRVN * DD * BB];          // pass3 results at drivers' neighbor slots
__device__ float g_zf[NDRVN * BB];               // pass4 results at drivers

// ---------------------------------------------------------------------------
// Packed f32x2 helpers
// ---------------------------------------------------------------------------
__device__ __forceinline__ u64 ffma2(u64 a, u64 b, u64 c) {
    u64 d;
    asm("fma.rn.f32x2 %0, %1, %2, %3;" : "=l"(d) : "l"(a), "l"(b), "l"(c));
    return d;
}
__device__ __forceinline__ u64 add2(u64 a, u64 b) {
    u64 d;
    asm("add.rn.f32x2 %0, %1, %2;" : "=l"(d) : "l"(a), "l"(b));
    return d;
}
__device__ __forceinline__ u64 relu2(u64 x) {
    unsigned lo, hi;
    asm("mov.b64 {%0,%1}, %2;" : "=r"(lo), "=r"(hi) : "l"(x));
    float a = fmaxf(__uint_as_float(lo), 0.0f);
    float b = fmaxf(__uint_as_float(hi), 0.0f);
    u64 r;
    asm("mov.b64 %0, {%1,%2};" : "=l"(r) : "r"(__float_as_uint(a)), "r"(__float_as_uint(b)));
    return r;
}
__device__ __forceinline__ u64 pack2(float w) {
    u64 r;
    unsigned u = __float_as_uint(w);
    asm("mov.b64 %0, {%1,%1};" : "=l"(r) : "r"(u));
    return r;
}

// ---------------------------------------------------------------------------
// Transpose x [B, N] -> g_zA [N, B]
// ---------------------------------------------------------------------------
__global__ void transpose_kernel(const float* __restrict__ x) {
    __shared__ float tile[32][33];
    int n0 = blockIdx.x * 32;
    int tx = threadIdx.x, ty = threadIdx.y;
    int n = n0 + tx;
    if (n < NNODES) tile[ty][tx] = x[ty * NNODES + n];
    __syncthreads();
    int n2 = n0 + ty;
    if (n2 < NNODES) g_zA[n2 * BB + tx] = tile[tx][ty];
}

// ===========================================================================
// FULL PASS (FFMA2 packed batch pairs) — proven R3 body
// ===========================================================================
template <int WIN>
__device__ __forceinline__ void mid_layer_p(u64 (&h)[FEAT][DD - 2],
                                            const u64* __restrict__ sw,
                                            const u64* __restrict__ sb) {
    #pragma unroll
    for (int w = 0; w < WIN - 2; w++) {
        u64 tmp[FEAT];
        #pragma unroll
        for (int co = 0; co < FEAT; co++) {
            u64 a = sb[co];
            #pragma unroll
            for (int ci = 0; ci < FEAT; ci++) {
                a = ffma2(sw[(co * FEAT + ci) * 3 + 0], h[ci][w + 0], a);
                a = ffma2(sw[(co * FEAT + ci) * 3 + 1], h[ci][w + 1], a);
                a = ffma2(sw[(co * FEAT + ci) * 3 + 2], h[ci][w + 2], a);
            }
            tmp[co] = relu2(a);
        }
        #pragma unroll
        for (int co = 0; co < FEAT; co++) h[co][w] = tmp[co];
    }
}

template <int SRC>   // SRC=0: g_zA -> g_zB;  SRC=1: g_zB -> g_zA
__global__ void __launch_bounds__(128)
pass_full(const int* __restrict__ nbr,
          const float* __restrict__ w_first, const float* __restrict__ b_first,
          const float* __restrict__ w_mid,   const float* __restrict__ b_mid,
          const float* __restrict__ w_last,  const float* __restrict__ b_last) {
    __shared__ u64 swf[FEAT * 3];
    __shared__ u64 sbf[FEAT];
    __shared__ u64 swm[NMID * FEAT * FEAT * 3];
    __shared__ u64 sbm[NMID * FEAT];
    __shared__ u64 swl[FEAT * 3];
    __shared__ u64 sbl[1];

    int t = threadIdx.x;
    if (t < FEAT * 3) swf[t] = pack2(w_first[t]);
    if (t < FEAT) sbf[t] = pack2(b_first[t]);
    for (int i = t; i < NMID * FEAT * FEAT * 3; i += blockDim.x) swm[i] = pack2(w_mid[i]);
    if (t < NMID * FEAT) sbm[t] = pack2(b_mid[t]);
    if (t < FEAT * 3) swl[t] = pack2(w_last[t]);
    if (t == 0) sbl[0] = pack2(b_last[0]);
    __syncthreads();

    const u64* __restrict__ zin = SRC == 0 ? (const u64*)g_zA : (const u64*)g_zB;
    u64* __restrict__ zout      = SRC == 0 ? (u64*)g_zB : (u64*)g_zA;

    unsigned gid = blockIdx.x * blockDim.x + threadIdx.x;
    if (gid >= (unsigned)NNODES * NPAIR) return;
    int n = gid >> 4;
    int p = gid & 15;

    u64 v[DD];
    const int* nb = nbr + n * DD;
    #pragma unroll
    for (int d = 0; d < DD; d++) {
        int idx = __ldg(&nb[d]);
        v[d] = __ldg(&zin[idx * NPAIR + p]);
    }

    u64 h[FEAT][DD - 2];
    #pragma unroll
    for (int c = 0; c < FEAT; c++) {
        #pragma unroll
        for (int w = 0; w < DD - 2; w++) {
            u64 a = sbf[c];
            a = ffma2(swf[c * 3 + 0], v[w + 0], a);
            a = ffma2(swf[c * 3 + 1], v[w + 1], a);
            a = ffma2(swf[c * 3 + 2], v[w + 2], a);
            h[c][w] = relu2(a);
        }
    }

    mid_layer_p<14>(h, swm + 0 * FEAT * FEAT * 3, sbm + 0 * FEAT);
    mid_layer_p<12>(h, swm + 1 * FEAT * FEAT * 3, sbm + 1 * FEAT);
    mid_layer_p<10>(h, swm + 2 * FEAT * FEAT * 3, sbm + 2 * FEAT);
    mid_layer_p<8>(h,  swm + 3 * FEAT * FEAT * 3, sbm + 3 * FEAT);
    mid_layer_p<6>(h,  swm + 4 * FEAT * FEAT * 3, sbm + 4 * FEAT);

    u64 o[2];
    #pragma unroll
    for (int w = 0; w < 2; w++) {
        u64 a = sbl[0];
        #pragma unroll
        for (int ci = 0; ci < FEAT; ci++) {
            a = ffma2(swl[ci * 3 + 0], h[ci][w + 0], a);
            a = ffma2(swl[ci * 3 + 1], h[ci][w + 1], a);
            a = ffma2(swl[ci * 3 + 2], h[ci][w + 2], a);
        }
        o[w] = relu2(a);
    }
    u64 s = add2(o[0], o[1]);
    zout[n * NPAIR + p] = ffma2(s, pack2(0.5f), pack2(0.0f));
}

// ===========================================================================
// SCALAR conv body (proven R4) — used by the lite passes
// ===========================================================================
struct SW {
    float swf[FEAT * 3]; float sbf[FEAT];
    float swm[NMID * FEAT * FEAT * 3]; float sbm[NMID * FEAT];
    float swl[FEAT * 3]; float sbl[1];
};

__device__ __forceinline__ void load_weights(SW* s,
        const float* __restrict__ w_first, const float* __restrict__ b_first,
        const float* __restrict__ w_mid,   const float* __restrict__ b_mid,
        const float* __restrict__ w_last,  const float* __restrict__ b_last,
        int t, int bs) {
    if (t < FEAT * 3) s->swf[t] = w_first[t];
    if (t < FEAT) s->sbf[t] = b_first[t];
    for (int i = t; i < NMID * FEAT * FEAT * 3; i += bs) s->swm[i] = w_mid[i];
    if (t < NMID * FEAT) s->sbm[t] = b_mid[t];
    if (t < FEAT * 3) s->swl[t] = w_last[t];
    if (t == 0) s->sbl[0] = b_last[0];
}

template <int WIN, int AW, int BW>
__device__ __forceinline__ void mid_layer_s(const float (&hin)[FEAT][AW],
                                            float (&hout)[FEAT][BW],
                                            const float* __restrict__ sw,
                                            const float* __restrict__ sb) {
    #pragma unroll
    for (int co = 0; co < FEAT; co++) {
        float wr[FEAT * 3];
        #pragma unroll
        for (int i = 0; i < FEAT * 3; i++) wr[i] = sw[(co * FEAT) * 3 + i];
        float bias = sb[co];
        #pragma unroll
        for (int w = 0; w < WIN - 2; w++) {
            float a = bias;
            #pragma unroll
            for (int ci = 0; ci < FEAT; ci++) {
                a = fmaf(wr[ci * 3 + 0], hin[ci][w + 0], a);
                a = fmaf(wr[ci * 3 + 1], hin[ci][w + 1], a);
                a = fmaf(wr[ci * 3 + 2], hin[ci][w + 2], a);
            }
            hout[co][w] = fmaxf(a, 0.0f);
        }
    }
}

__device__ __forceinline__ float conv_stack(const float (&v)[DD], const SW* s) {
    float hA[FEAT][14];
    #pragma unroll
    for (int c = 0; c < FEAT; c++) {
        float w0 = s->swf[c * 3 + 0], w1 = s->swf[c * 3 + 1], w2 = s->swf[c * 3 + 2];
        float bias = s->sbf[c];
        #pragma unroll
        for (int w = 0; w < 14; w++) {
            float a = bias;
            a = fmaf(w0, v[w + 0], a);
            a = fmaf(w1, v[w + 1], a);
            a = fmaf(w2, v[w + 2], a);
            hA[c][w] = fmaxf(a, 0.0f);
        }
    }
    float hB[FEAT][12];
    mid_layer_s<14>(hA, hB, s->swm + 0 * FEAT * FEAT * 3, s->sbm + 0 * FEAT);
    mid_layer_s<12>(hB, hA, s->swm + 1 * FEAT * FEAT * 3, s->sbm + 1 * FEAT);
    mid_layer_s<10>(hA, hB, s->swm + 2 * FEAT * FEAT * 3, s->sbm + 2 * FEAT);
    mid_layer_s<8>(hB, hA,  s->swm + 3 * FEAT * FEAT * 3, s->sbm + 3 * FEAT);
    mid_layer_s<6>(hA, hB,  s->swm + 4 * FEAT * FEAT * 3, s->sbm + 4 * FEAT);

    float o[2];
    #pragma unroll
    for (int w = 0; w < 2; w++) {
        float a = s->sbl[0];
        #pragma unroll
        for (int ci = 0; ci < FEAT; ci++) {
            a = fmaf(s->swl[ci * 3 + 0], hB[ci][w + 0], a);
            a = fmaf(s->swl[ci * 3 + 1], hB[ci][w + 1], a);
            a = fmaf(s->swl[ci * 3 + 2], hB[ci][w + 2], a);
        }
        o[w] = fmaxf(a, 0.0f);
    }
    return 0.5f * (o[0] + o[1]);
}

// ---------------------------------------------------------------------------
// Pass 3 (lite): compute z3 only at the 500x16 driver-neighbor slots.
// warp = (driver d, slot j); node m = nbr[drivers[d]*16 + j]; reads g_zA (z2).
// ---------------------------------------------------------------------------
__global__ void __launch_bounds__(128)
pass3_lite(const int* __restrict__ nbr, const int* __restrict__ drivers,
           const float* __restrict__ w_first, const float* __restrict__ b_first,
           const float* __restrict__ w_mid,   const float* __restrict__ b_mid,
           const float* __restrict__ w_last,  const float* __restrict__ b_last) {
    __shared__ SW s;
    load_weights(&s, w_first, b_first, w_mid, b_mid, w_last, b_last,
                 threadIdx.x, blockDim.x);
    __syncthreads();

    unsigned gid = blockIdx.x * blockDim.x + threadIdx.x;
    if (gid >= (unsigned)NDRVN * DD * BB) return;
    int job = gid >> 5;              // 0 .. 7999  (= d*16 + j), warp-uniform
    int b = gid & 31;

    int d = job >> 4;
    int j = job & 15;
    int m = __ldg(&nbr[__ldg(&drivers[d]) * DD + j]);   // node whose z3 we need

    float v[DD];
    const int* nb = nbr + m * DD;
    #pragma unroll
    for (int k = 0; k < DD; k++) {
        int idx = __ldg(&nb[k]);
        v[k] = __ldg(&g_zA[idx * BB + b]);
    }
    g_z3[job * BB + b] = conv_stack(v, &s);
}

// ---------------------------------------------------------------------------
// Pass 4 (lite): only the 500 driver nodes. Inputs come straight from g_z3
// rows (already in the driver's neighbor order) — no gather needed.
// ---------------------------------------------------------------------------
__global__ void __launch_bounds__(128)
pass4_lite(const float* __restrict__ w_first, const float* __restrict__ b_first,
           const float* __restrict__ w_mid,   const float* __restrict__ b_mid,
           const float* __restrict__ w_last,  const float* __restrict__ b_last) {
    __shared__ SW s;
    load_weights(&s, w_first, b_first, w_mid, b_mid, w_last, b_last,
                 threadIdx.x, blockDim.x);
    __syncthreads();

    unsigned gid = blockIdx.x * blockDim.x + threadIdx.x;
    if (gid >= (unsigned)NDRVN * BB) return;
    int d = gid >> 5;
    int b = gid & 31;

    float v[DD];
    #pragma unroll
    for (int k = 0; k < DD; k++)
        v[k] = __ldg(&g_z3[(d * DD + k) * BB + b]);
    g_zf[d * BB + b] = conv_stack(v, &s);
}

// ---------------------------------------------------------------------------
__global__ void zero_kernel(float4* __restrict__ out, int n4) {
    int i = blockIdx.x * blockDim.x + threadIdx.x;
    if (i < n4) out[i] = make_float4(0.f, 0.f, 0.f, 0.f);
}

// ---------------------------------------------------------------------------
// Masked softmax over driver columns; reads g_zf [500][B]
// ---------------------------------------------------------------------------
__global__ void softmax_kernel(const int* __restrict__ drivers,
                               float* __restrict__ out) {
    __shared__ float red[512];
    int b = blockIdx.x;
    int t = threadIdx.x;

    float myv = 0.0f;
    int drv = -1;
    float mval = -INFINITY;
    if (t < NDRVN) {
        drv = drivers[t];
        myv = g_zf[t * BB + b];
        mval = myv;
    }
    red[t] = mval;
    __syncthreads();
    #pragma unroll
    for (int s = 256; s > 0; s >>= 1) {
        if (t < s) red[t] = fmaxf(red[t], red[t + s]);
        __syncthreads();
    }
    float m = fmaxf(red[0], 0.0f);
    __syncthreads();

    float e = (t < NDRVN) ? expf(myv - m) : 0.0f;
    red[t] = e;
    __syncthreads();
    #pragma unroll
    for (int s = 256; s > 0; s >>= 1) {
        if (t < s) red[t] += red[t + s];
        __syncthreads();
    }
    float Z = red[0] + (float)(NNODES - NDRVN) * expf(-m);

    if (t < NDRVN) out[b * NNODES + drv] = e / Z;
}

// ---------------------------------------------------------------------------
extern "C" void kernel_launch(void* const* d_in, const int* in_sizes, int n_in,
                              void* d_out, int out_size) {
    const float* x       = (const float*)d_in[0];
    const int*   nbr     = (const int*)  d_in[1];
    const int*   drivers = (const int*)  d_in[2];
    // d_in[3] = driver_matrix (unused)
    const float* w_first = (const float*)d_in[4];
    const float* b_first = (const float*)d_in[5];
    const float* w_mid   = (const float*)d_in[6];
    const float* b_mid   = (const float*)d_in[7];
    const float* w_last  = (const float*)d_in[8];
    const float* b_last  = (const float*)d_in[9];
    float* out = (float*)d_out;

    transpose_kernel<<<(NNODES + 31) / 32, dim3(32, 32)>>>(x);

    const int blk = 128;
    const int grid_full = (NNODES * NPAIR + blk - 1) / blk;   // packed threads

    // Passes 1-2: full graph (FFMA2 packed).  zA -> zB -> zA
    pass_full<0><<<grid_full, blk>>>(nbr, w_first, b_first, w_mid, b_mid, w_last, b_last);
    pass_full<1><<<grid_full, blk>>>(nbr, w_first, b_first, w_mid, b_mid, w_last, b_last);

    // Pass 3: only at drivers' neighbors (500*16 jobs)
    const int grid3 = (NDRVN * DD * BB + blk - 1) / blk;      // 2000 blocks
    pass3_lite<<<grid3, blk>>>(nbr, drivers, w_first, b_first, w_mid, b_mid, w_last, b_last);

    // Pass 4: only at drivers (500 jobs)
    const int grid4 = (NDRVN * BB + blk - 1) / blk;           // 125 blocks
    pass4_lite<<<grid4, blk>>>(w_first, b_first, w_mid, b_mid, w_last, b_last);

    int n4 = NNODES * BB / 4;
    zero_kernel<<<(n4 + 255) / 256, 256>>>((float4*)out, n4);
    softmax_kernel<<<BB, 512>>>(drivers, out);
}